// round 4
// baseline (speedup 1.0000x reference)
#include <cuda_runtime.h>
#include <cuda_fp16.h>
#include <math_constants.h>
#include <cstdint>

#define Bq 4
#define Tq 1024
#define Cq 16
#define Dq 256
#define NHEADS (Bq*Cq)          // 64
#define MTOT (Bq*Tq*Cq)         // 65536 tokens

// f16 scratch
__device__ __align__(128) __half g_xb[(size_t)MTOT * Dq];
__device__ __align__(128) __half g_wb[3 * Dq * Dq];              // wq|wk|wv [n][k]
__device__ __align__(128) __half g_q [(size_t)NHEADS * Tq * Dq]; // [h][t][d]
__device__ __align__(128) __half g_k [(size_t)NHEADS * Tq * Dq]; // [h][t][d]
__device__ __align__(128) __half g_v [(size_t)NHEADS * Tq * Dq]; // [h][t][d]
__device__ __align__(128) unsigned char g_mt[NHEADS * Tq];       // mask [h][t]

// ---------------------------------------------------------------------------
// helpers
// ---------------------------------------------------------------------------
static __device__ __forceinline__ unsigned packh(float a, float b) {
    __half2 h = __floats2half2_rn(a, b);
    return *reinterpret_cast<unsigned*>(&h);
}
static __device__ __forceinline__ float2 unph(unsigned u) {
    __half2 h = *reinterpret_cast<__half2*>(&u);
    return __half22float2(h);
}
static __device__ __forceinline__ unsigned hmul2u(unsigned a, unsigned b) {
    __half2 r = __hmul2(*reinterpret_cast<__half2*>(&a),
                        *reinterpret_cast<__half2*>(&b));
    return *reinterpret_cast<unsigned*>(&r);
}

static __device__ __forceinline__ void mma_f16_f32(
    float& d0, float& d1, float& d2, float& d3,
    unsigned a0, unsigned a1, unsigned a2, unsigned a3,
    unsigned b0, unsigned b1)
{
    asm volatile(
        "mma.sync.aligned.m16n8k16.row.col.f32.f16.f16.f32 "
        "{%0,%1,%2,%3}, {%4,%5,%6,%7}, {%8,%9}, {%0,%1,%2,%3};\n"
        : "+f"(d0), "+f"(d1), "+f"(d2), "+f"(d3)
        : "r"(a0), "r"(a1), "r"(a2), "r"(a3), "r"(b0), "r"(b1));
}
static __device__ __forceinline__ void mma_f16_f16(
    unsigned& d0, unsigned& d1,
    unsigned a0, unsigned a1, unsigned a2, unsigned a3,
    unsigned b0, unsigned b1)
{
    asm volatile(
        "mma.sync.aligned.m16n8k16.row.col.f16.f16.f16.f16 "
        "{%0,%1}, {%2,%3,%4,%5}, {%6,%7}, {%0,%1};\n"
        : "+r"(d0), "+r"(d1)
        : "r"(a0), "r"(a1), "r"(a2), "r"(a3), "r"(b0), "r"(b1));
}
static __device__ __forceinline__ void ldsm_x4(
    unsigned& r0, unsigned& r1, unsigned& r2, unsigned& r3, unsigned addr)
{
    asm volatile("ldmatrix.sync.aligned.m8n8.x4.shared.b16 {%0,%1,%2,%3}, [%4];"
        : "=r"(r0), "=r"(r1), "=r"(r2), "=r"(r3) : "r"(addr));
}
static __device__ __forceinline__ void ldsm_x4_t(
    unsigned& r0, unsigned& r1, unsigned& r2, unsigned& r3, unsigned addr)
{
    asm volatile("ldmatrix.sync.aligned.m8n8.x4.trans.shared.b16 {%0,%1,%2,%3}, [%4];"
        : "=r"(r0), "=r"(r1), "=r"(r2), "=r"(r3) : "r"(addr));
}

#define CPA16(d, s) asm volatile("cp.async.cg.shared.global [%0], [%1], 16;" :: "r"(d), "l"(s))
#define CP_COMMIT() asm volatile("cp.async.commit_group;")
#define CP_WAIT(n)  asm volatile("cp.async.wait_group %0;" :: "n"(n))

// ---------------------------------------------------------------------------
// Converters
// ---------------------------------------------------------------------------
__global__ void conv_x_kernel(const float* __restrict__ x)
{
    int i = blockIdx.x * blockDim.x + threadIdx.x;   // float4 index
    const float4 v = ((const float4*)x)[i];
    ((uint2*)g_xb)[i] = make_uint2(packh(v.x, v.y), packh(v.z, v.w));
}
__global__ void conv_w_kernel(const float* __restrict__ wq,
                              const float* __restrict__ wk,
                              const float* __restrict__ wv)
{
    int i = blockIdx.x * blockDim.x + threadIdx.x;   // 0..65535
    g_wb[i]          = __float2half(wq[i]);
    g_wb[i + 65536]  = __float2half(wk[i]);
    g_wb[i + 131072] = __float2half(wv[i]);
}
__global__ void conv_m_kernel(const unsigned char* __restrict__ xmask)
{
    int i = blockIdx.x * blockDim.x + threadIdx.x;   // 0..65535
    int h = i >> 10, t = i & 1023;
    int b = h >> 4,  c = h & 15;
    g_mt[i] = xmask[(size_t)((b << 10) + t) * Cq + c];
}

// ---------------------------------------------------------------------------
// Kernel 1: QKV projection (f16 HMMA, f32 accum) + bias + RoPE.
// CTA tile 128(M) x 64(N), K=256. All outputs stored coalesced [h][t][d].
// ---------------------------------------------------------------------------
#define XS 264
#define WS 264

__global__ __launch_bounds__(256, 1) void qkv_tc_kernel(
    const int*   __restrict__ pos,
    const float* __restrict__ pe,
    const float* __restrict__ bq,
    const float* __restrict__ bk,
    const float* __restrict__ bv)
{
    extern __shared__ char smraw[];
    __half* sX = (__half*)smraw;          // 128 x XS
    __half* sW = sX + 128 * XS;           // 64 x WS

    const int tid  = threadIdx.x;
    const int w    = tid >> 5;
    const int lane = tid & 31;
    const int q    = lane & 3;
    const int lr   = lane >> 2;

    const int mtile = blockIdx.y;
    const int bx    = blockIdx.x;          // 0..11
    const int mat   = bx >> 2;
    const int n0    = (bx & 3) * 64;
    const int m0    = mtile * 128;

    const __half* xb = g_xb + (size_t)m0 * Dq;
#pragma unroll
    for (int it = 0; it < 32; ++it) {
        int idx = it * 256 + tid;
        int row = idx >> 6, c4 = idx & 63;
        *(uint2*)&sX[row * XS + c4 * 4] = *(const uint2*)(xb + row * Dq + c4 * 4);
    }
    const __half* wb = g_wb + mat * 65536 + n0 * Dq;
#pragma unroll
    for (int it = 0; it < 16; ++it) {
        int idx = it * 256 + tid;
        int row = idx >> 6, c4 = idx & 63;
        *(uint2*)&sW[row * WS + c4 * 4] = *(const uint2*)(wb + row * Dq + c4 * 4);
    }
    __syncthreads();

    float acc[8][4];
#pragma unroll
    for (int nf = 0; nf < 8; ++nf)
#pragma unroll
        for (int j = 0; j < 4; ++j) acc[nf][j] = 0.f;

    const int g  = lane >> 3;
    const int r8 = lane & 7;
    unsigned smem_u = (unsigned)__cvta_generic_to_shared(smraw);
    // A frags via ldmatrix: rows = m, cols = k
    const unsigned qa_off = smem_u +
        ((unsigned)(w * 16 + (g & 1) * 8 + r8) * XS + (g >> 1) * 8) * 2;
    // B frags via ldmatrix: rows = n, cols = k
    const unsigned kb_off = smem_u + 128 * XS * 2 +
        ((unsigned)((g >> 1) * 8 + r8) * WS + (g & 1) * 8) * 2;

#pragma unroll
    for (int kk = 0; kk < 16; ++kk) {
        unsigned a0, a1, a2, a3;
        ldsm_x4(a0, a1, a2, a3, qa_off + kk * 32);
#pragma unroll
        for (int ng = 0; ng < 4; ++ng) {
            unsigned b0, b1, b2, b3;
            ldsm_x4(b0, b1, b2, b3, kb_off + ng * 16 * WS * 2 + kk * 32);
            mma_f16_f32(acc[2*ng][0], acc[2*ng][1], acc[2*ng][2], acc[2*ng][3],
                        a0, a1, a2, a3, b0, b1);
            mma_f16_f32(acc[2*ng+1][0], acc[2*ng+1][1], acc[2*ng+1][2], acc[2*ng+1][3],
                        a0, a1, a2, a3, b2, b3);
        }
    }

    const float* bias = (mat == 0) ? bq : (mat == 1) ? bk : bv;
    const int tokA = m0 + w * 16 + lr;
    const int tokB = tokA + 8;
    const int bA = tokA >> 14, tA = (tokA >> 4) & (Tq - 1), cA = tokA & (Cq - 1);
    const int bB = tokB >> 14, tB = (tokB >> 4) & (Tq - 1), cB = tokB & (Cq - 1);
    const int hA = bA * Cq + cA, hB = bB * Cq + cB;

    int pA = 0, pB = 0;
    if (mat < 2) { pA = pos[tokA]; pB = pos[tokB]; }

    __half* outp = (mat == 0) ? g_q : (mat == 1) ? g_k : g_v;

#pragma unroll
    for (int nf = 0; nf < 8; ++nf) {
        const int c = n0 + nf * 8 + 2 * q;                  // even
        const float2 bb = *(const float2*)(bias + c);
        float v0 = acc[nf][0] + bb.x, v1 = acc[nf][1] + bb.y;   // row A
        float v2 = acc[nf][2] + bb.x, v3 = acc[nf][3] + bb.y;   // row B
        if (mat < 2) {
            const float2 csA = *(const float2*)(pe + (size_t)pA * Dq + c);
            const float2 csB = *(const float2*)(pe + (size_t)pB * Dq + c);
            float r0 = v0 * csA.x - v1 * csA.y;
            float r1 = v0 * csA.y + v1 * csA.x;
            float r2 = v2 * csB.x - v3 * csB.y;
            float r3 = v2 * csB.y + v3 * csB.x;
            v0 = r0; v1 = r1; v2 = r2; v3 = r3;
        }
        *(unsigned*)&outp[((size_t)hA * Tq + tA) * Dq + c] = packh(v0, v1);
        *(unsigned*)&outp[((size_t)hB * Tq + tB) * Dq + c] = packh(v2, v3);
    }
}

// ---------------------------------------------------------------------------
// Kernel 2: flash attention, f16 HMMA with f16 accumulators, Q frags in
// registers, ldmatrix fragment loads, 2-stage cp.async K/V pipeline,
// fused residual + LayerScale + LayerNorm epilogue.
// CTA = (head, 128 q-rows); 8 warps x 16 q-rows; K-tiles of 64, 16 iters.
// ---------------------------------------------------------------------------
#define STR 264
#define KBYTES (64 * STR * 2)      // 33792 one K (or V) tile
#define STAGEB (2 * KBYTES)        // 67584 per stage

__global__ __launch_bounds__(256, 1) void attn_tc_kernel(
    const float* __restrict__ x,
    const float* __restrict__ lng,
    const float* __restrict__ lnb,
    const float* __restrict__ lsg,
    float* __restrict__ out)
{
    extern __shared__ char smraw[];
    unsigned char* sQm = (unsigned char*)(smraw + 2 * STAGEB);   // 128
    unsigned char* sKm = sQm + 128;                               // 2 x 64
    const unsigned smem_u = (unsigned)__cvta_generic_to_shared(smraw);
    const unsigned sqm_u  = smem_u + 2 * STAGEB;
    const unsigned skm_u  = sqm_u + 128;

    const int tid  = threadIdx.x;
    const int w    = tid >> 5;
    const int lane = tid & 31;
    const int q    = lane & 3;
    const int lr   = lane >> 2;
    const int g    = lane >> 3;
    const int r8   = lane & 7;

    const int h  = blockIdx.y;
    const int b  = h >> 4, c = h & 15;
    const int q0 = blockIdx.x * 128;

    const __half* qg = g_q + ((size_t)h * Tq + q0) * Dq;
    const __half* kg = g_k + (size_t)h * Tq * Dq;
    const __half* vg = g_v + (size_t)h * Tq * Dq;
    const unsigned char* mg = g_mt + h * Tq;

    // ---- stage Q (128x256) into stage-1 region, plus q-mask ----
    const unsigned qs = smem_u + STAGEB;
#pragma unroll
    for (int it = 0; it < 16; ++it) {
        int idx = it * 256 + tid;
        int row = idx >> 5, cc = idx & 31;
        CPA16(qs + (unsigned)(row * STR * 2 + cc * 16), qg + row * Dq + cc * 8);
    }
    if (tid < 8) CPA16(sqm_u + tid * 16, mg + q0 + tid * 16);
    CP_COMMIT();
    CP_WAIT(0);
    __syncthreads();

    // ---- Q fragments -> registers (16 k-groups x 4 regs) ----
    unsigned qf[16][4];
    const unsigned qa_off = qs +
        ((unsigned)(w * 16 + (g & 1) * 8 + r8) * STR + (g >> 1) * 8) * 2;
#pragma unroll
    for (int kk = 0; kk < 16; ++kk)
        ldsm_x4(qf[kk][0], qf[kk][1], qf[kk][2], qf[kk][3], qa_off + kk * 32);
    const int qmA = sQm[w * 16 + lr];
    const int qmB = sQm[w * 16 + lr + 8];
    __syncthreads();   // all warps done with stage-1 region

    // ---- issue kt=0, kt=1 ----
    auto issue = [&](int kt) {
        const int stage = kt & 1;
        const unsigned sb = smem_u + stage * STAGEB;
        const int k0 = kt * 64;
#pragma unroll
        for (int it = 0; it < 8; ++it) {
            int idx = it * 256 + tid;
            int row = idx >> 5, cc = idx & 31;
            CPA16(sb + (unsigned)(row * STR * 2 + cc * 16),
                  kg + (size_t)(k0 + row) * Dq + cc * 8);
            CPA16(sb + KBYTES + (unsigned)(row * STR * 2 + cc * 16),
                  vg + (size_t)(k0 + row) * Dq + cc * 8);
        }
        if (tid < 4) CPA16(skm_u + stage * 64 + tid * 16, mg + k0 + tid * 16);
    };
    issue(0); CP_COMMIT();
    issue(1); CP_COMMIT();

    // fragment lane offsets
    const unsigned koff = ((unsigned)((g >> 1) * 8 + r8) * STR + (g & 1) * 8) * 2;
    const unsigned voff = ((unsigned)((g & 1) * 8 + r8) * STR + (g >> 1) * 8) * 2;

    unsigned oacc[32][2];
#pragma unroll
    for (int j = 0; j < 32; ++j) { oacc[j][0] = 0u; oacc[j][1] = 0u; }
    float mrunA = -CUDART_INF_F, mrunB = -CUDART_INF_F;
    float lsumA = 0.f, lsumB = 0.f;

    for (int kt = 0; kt < 16; ++kt) {
        CP_WAIT(1);
        __syncthreads();
        const int stage = kt & 1;
        const unsigned kb_s = smem_u + stage * STAGEB;
        const unsigned vb_s = kb_s + KBYTES;
        const unsigned char* km = sKm + stage * 64;

        // ---- S = Q K^T (f16 accum) ----
        unsigned sacc[8][2];
#pragma unroll
        for (int nf = 0; nf < 8; ++nf) { sacc[nf][0] = 0u; sacc[nf][1] = 0u; }
#pragma unroll
        for (int kk = 0; kk < 16; ++kk) {
#pragma unroll
            for (int ng = 0; ng < 4; ++ng) {
                unsigned b0, b1, b2, b3;
                ldsm_x4(b0, b1, b2, b3,
                        kb_s + (unsigned)(ng * 16 * STR * 2) + kk * 32 + koff);
                mma_f16_f16(sacc[2*ng][0],   sacc[2*ng][1],
                            qf[kk][0], qf[kk][1], qf[kk][2], qf[kk][3], b0, b1);
                mma_f16_f16(sacc[2*ng+1][0], sacc[2*ng+1][1],
                            qf[kk][0], qf[kk][1], qf[kk][2], qf[kk][3], b2, b3);
            }
        }

        // ---- mask + scale + row max ----
        float sv[8][4];
        float tmaxA = -CUDART_INF_F, tmaxB = -CUDART_INF_F;
#pragma unroll
        for (int nf = 0; nf < 8; ++nf) {
            const float2 lo = unph(sacc[nf][0]);   // row lr
            const float2 hi = unph(sacc[nf][1]);   // row lr+8
            const int cc = nf * 8 + 2 * q;
            const int k0m = km[cc], k1m = km[cc + 1];
            sv[nf][0] = (qmA | k0m) ? -CUDART_INF_F : lo.x * 0.0625f;
            sv[nf][1] = (qmA | k1m) ? -CUDART_INF_F : lo.y * 0.0625f;
            sv[nf][2] = (qmB | k0m) ? -CUDART_INF_F : hi.x * 0.0625f;
            sv[nf][3] = (qmB | k1m) ? -CUDART_INF_F : hi.y * 0.0625f;
            tmaxA = fmaxf(tmaxA, fmaxf(sv[nf][0], sv[nf][1]));
            tmaxB = fmaxf(tmaxB, fmaxf(sv[nf][2], sv[nf][3]));
        }
        tmaxA = fmaxf(tmaxA, __shfl_xor_sync(0xffffffffu, tmaxA, 1));
        tmaxA = fmaxf(tmaxA, __shfl_xor_sync(0xffffffffu, tmaxA, 2));
        tmaxB = fmaxf(tmaxB, __shfl_xor_sync(0xffffffffu, tmaxB, 1));
        tmaxB = fmaxf(tmaxB, __shfl_xor_sync(0xffffffffu, tmaxB, 2));

        const float mnA = fmaxf(mrunA, tmaxA);
        const float mnB = fmaxf(mrunB, tmaxB);
        const float corrA = (mnA == -CUDART_INF_F) ? 1.f : __expf(mrunA - mnA);
        const float corrB = (mnB == -CUDART_INF_F) ? 1.f : __expf(mrunB - mnB);
        const float mUA = (mnA == -CUDART_INF_F) ? 0.f : mnA;
        const float mUB = (mnB == -CUDART_INF_F) ? 0.f : mnB;
        lsumA *= corrA; lsumB *= corrB;
        mrunA = mnA; mrunB = mnB;

        unsigned pa[4][4];
#pragma unroll
        for (int kk = 0; kk < 4; ++kk) {
            float p00 = __expf(sv[2*kk][0]   - mUA);
            float p01 = __expf(sv[2*kk][1]   - mUA);
            float p02 = __expf(sv[2*kk][2]   - mUB);
            float p03 = __expf(sv[2*kk][3]   - mUB);
            float p10 = __expf(sv[2*kk+1][0] - mUA);
            float p11 = __expf(sv[2*kk+1][1] - mUA);
            float p12 = __expf(sv[2*kk+1][2] - mUB);
            float p13 = __expf(sv[2*kk+1][3] - mUB);
            lsumA += p00 + p01 + p10 + p11;
            lsumB += p02 + p03 + p12 + p13;
            pa[kk][0] = packh(p00, p01);
            pa[kk][1] = packh(p02, p03);
            pa[kk][2] = packh(p10, p11);
            pa[kk][3] = packh(p12, p13);
        }

        // rescale O (half2)
        const unsigned cA2 = packh(corrA, corrA);
        const unsigned cB2 = packh(corrB, corrB);
#pragma unroll
        for (int j = 0; j < 32; ++j) {
            oacc[j][0] = hmul2u(oacc[j][0], cA2);
            oacc[j][1] = hmul2u(oacc[j][1], cB2);
        }

        // ---- O += P V  (V frags via ldmatrix.trans) ----
#pragma unroll
        for (int kk = 0; kk < 4; ++kk) {
#pragma unroll
            for (int dg = 0; dg < 16; ++dg) {
                unsigned v0, v1, v2, v3;
                ldsm_x4_t(v0, v1, v2, v3,
                          vb_s + (unsigned)(kk * 16 * STR * 2) + dg * 32 + voff);
                mma_f16_f16(oacc[2*dg][0],   oacc[2*dg][1],
                            pa[kk][0], pa[kk][1], pa[kk][2], pa[kk][3], v0, v1);
                mma_f16_f16(oacc[2*dg+1][0], oacc[2*dg+1][1],
                            pa[kk][0], pa[kk][1], pa[kk][2], pa[kk][3], v2, v3);
            }
        }
        __syncthreads();
        if (kt + 2 < 16) issue(kt + 2);
        CP_COMMIT();
    }

    // ---- epilogue ----
    lsumA += __shfl_xor_sync(0xffffffffu, lsumA, 1);
    lsumA += __shfl_xor_sync(0xffffffffu, lsumA, 2);
    lsumB += __shfl_xor_sync(0xffffffffu, lsumB, 1);
    lsumB += __shfl_xor_sync(0xffffffffu, lsumB, 2);
    const float invA = (lsumA > 0.f) ? (1.f / lsumA) : 0.f;
    const float invB = (lsumB > 0.f) ? (1.f / lsumB) : 0.f;

    const int gtA = q0 + w * 16 + lr;
    const int gtB = gtA + 8;
    const size_t miA = (size_t)(b * Tq + gtA) * Cq + c;
    const size_t miB = (size_t)(b * Tq + gtB) * Cq + c;
    const float* xA = x + miA * Dq;
    const float* xB = x + miB * Dq;

    float yv[32][4];
    float sumA = 0.f, ssqA = 0.f, sumB = 0.f, ssqB = 0.f;
#pragma unroll
    for (int j = 0; j < 32; ++j) {
        const int cc = j * 8 + 2 * q;
        const float2 g2 = *(const float2*)(lsg + cc);
        const float2 xa = *(const float2*)(xA + cc);
        const float2 xb2 = *(const float2*)(xB + cc);
        const float2 oa = unph(oacc[j][0]);
        const float2 ob = unph(oacc[j][1]);
        float y0 = xa.x  + g2.x * (oa.x * invA);
        float y1 = xa.y  + g2.y * (oa.y * invA);
        float y2 = xb2.x + g2.x * (ob.x * invB);
        float y3 = xb2.y + g2.y * (ob.y * invB);
        yv[j][0] = y0; yv[j][1] = y1; yv[j][2] = y2; yv[j][3] = y3;
        sumA += y0 + y1;  ssqA += y0 * y0 + y1 * y1;
        sumB += y2 + y3;  ssqB += y2 * y2 + y3 * y3;
    }
    sumA += __shfl_xor_sync(0xffffffffu, sumA, 1);
    sumA += __shfl_xor_sync(0xffffffffu, sumA, 2);
    ssqA += __shfl_xor_sync(0xffffffffu, ssqA, 1);
    ssqA += __shfl_xor_sync(0xffffffffu, ssqA, 2);
    sumB += __shfl_xor_sync(0xffffffffu, sumB, 1);
    sumB += __shfl_xor_sync(0xffffffffu, sumB, 2);
    ssqB += __shfl_xor_sync(0xffffffffu, ssqB, 1);
    ssqB += __shfl_xor_sync(0xffffffffu, ssqB, 2);

    const float muA = sumA * (1.f / 256.f);
    const float muB = sumB * (1.f / 256.f);
    const float rsA = rsqrtf(ssqA * (1.f / 256.f) - muA * muA + 1e-5f);
    const float rsB = rsqrtf(ssqB * (1.f / 256.f) - muB * muB + 1e-5f);

    float* oA = out + miA * Dq;
    float* oB = out + miB * Dq;
#pragma unroll
    for (int j = 0; j < 32; ++j) {
        const int cc = j * 8 + 2 * q;
        const float2 gg = *(const float2*)(lng + cc);
        const float2 bb = *(const float2*)(lnb + cc);
        float2 r0, r1;
        r0.x = (yv[j][0] - muA) * rsA * gg.x + bb.x;
        r0.y = (yv[j][1] - muA) * rsA * gg.y + bb.y;
        r1.x = (yv[j][2] - muB) * rsB * gg.x + bb.x;
        r1.y = (yv[j][3] - muB) * rsB * gg.y + bb.y;
        *(float2*)(oA + cc) = r0;
        *(float2*)(oB + cc) = r1;
    }
}

// ---------------------------------------------------------------------------
// Launcher. Inputs: 0 x, 1 x_mask(u8), 2 pos(i32), 3 pe, 4 wq_w, 5 wq_b,
// 6 wk_w, 7 wk_b, 8 wv_w, 9 wv_b, 10 ln_g, 11 ln_b, 12 ls_gamma
// ---------------------------------------------------------------------------
extern "C" void kernel_launch(void* const* d_in, const int* in_sizes, int n_in,
                              void* d_out, int out_size)
{
    const float* x   = (const float*)d_in[0];
    const unsigned char* xmask = (const unsigned char*)d_in[1];
    const int*   pos = (const int*)d_in[2];
    const float* pe  = (const float*)d_in[3];
    const float* wq  = (const float*)d_in[4];
    const float* bq  = (const float*)d_in[5];
    const float* wk  = (const float*)d_in[6];
    const float* bk  = (const float*)d_in[7];
    const float* wv  = (const float*)d_in[8];
    const float* bv  = (const float*)d_in[9];
    const float* lng = (const float*)d_in[10];
    const float* lnb = (const float*)d_in[11];
    const float* lsg = (const float*)d_in[12];
    float* out = (float*)d_out;

    conv_x_kernel<<<(MTOT * Dq / 4) / 256, 256>>>(x);
    conv_w_kernel<<<(Dq * Dq) / 256, 256>>>(wq, wk, wv);
    conv_m_kernel<<<(NHEADS * Tq) / 256, 256>>>(xmask);

    const int smem1 = (128 * XS + 64 * WS) * 2;
    cudaFuncSetAttribute(qkv_tc_kernel,
                         cudaFuncAttributeMaxDynamicSharedMemorySize, smem1);
    qkv_tc_kernel<<<dim3(12, MTOT / 128), 256, smem1>>>(pos, pe, bq, bk, bv);

    const int smem2 = 2 * STAGEB + 256;
    cudaFuncSetAttribute(attn_tc_kernel,
                         cudaFuncAttributeMaxDynamicSharedMemorySize, smem2);
    attn_tc_kernel<<<dim3(Tq / 128, NHEADS), 256, smem2>>>(
        x, lng, lnb, lsg, out);
}

// round 6
// speedup vs baseline: 1.1456x; 1.1456x over previous
#include <cuda_runtime.h>
#include <cuda_fp16.h>
#include <math_constants.h>
#include <cstdint>

#define Bq 4
#define Tq 1024
#define Cq 16
#define Dq 256
#define NHEADS (Bq*Cq)
#define MTOT (Bq*Tq*Cq)

__device__ __align__(128) __half g_xb[(size_t)MTOT * Dq];
__device__ __align__(128) __half g_wb[3 * Dq * Dq];
__device__ __align__(128) __half g_q [(size_t)NHEADS * Tq * Dq];
__device__ __align__(128) __half g_k [(size_t)NHEADS * Tq * Dq];
__device__ __align__(128) __half g_v [(size_t)NHEADS * Tq * Dq];
__device__ __align__(128) unsigned char g_mt[NHEADS * Tq];

static __device__ __forceinline__ unsigned packh(float a, float b) {
    __half2 h = __floats2half2_rn(a, b);
    return *reinterpret_cast<unsigned*>(&h);
}
static __device__ __forceinline__ float2 unph(unsigned u) {
    __half2 h = *reinterpret_cast<__half2*>(&u);
    return __half22float2(h);
}
static __device__ __forceinline__ unsigned hmul2u(unsigned a, unsigned b) {
    __half2 r = __hmul2(*reinterpret_cast<__half2*>(&a),
                        *reinterpret_cast<__half2*>(&b));
    return *reinterpret_cast<unsigned*>(&r);
}
static __device__ __forceinline__ void mma_f16_f16(
    unsigned& d0, unsigned& d1,
    unsigned a0, unsigned a1, unsigned a2, unsigned a3,
    unsigned b0, unsigned b1)
{
    asm volatile(
        "mma.sync.aligned.m16n8k16.row.col.f16.f16.f16.f16 "
        "{%0,%1}, {%2,%3,%4,%5}, {%6,%7}, {%0,%1};\n"
        : "+r"(d0), "+r"(d1)
        : "r"(a0), "r"(a1), "r"(a2), "r"(a3), "r"(b0), "r"(b1));
}
static __device__ __forceinline__ void ldsm_x4(
    unsigned& r0, unsigned& r1, unsigned& r2, unsigned& r3, unsigned addr)
{
    asm volatile("ldmatrix.sync.aligned.m8n8.x4.shared.b16 {%0,%1,%2,%3}, [%4];"
        : "=r"(r0), "=r"(r1), "=r"(r2), "=r"(r3) : "r"(addr));
}
static __device__ __forceinline__ void ldsm_x4_t(
    unsigned& r0, unsigned& r1, unsigned& r2, unsigned& r3, unsigned addr)
{
    asm volatile("ldmatrix.sync.aligned.m8n8.x4.trans.shared.b16 {%0,%1,%2,%3}, [%4];"
        : "=r"(r0), "=r"(r1), "=r"(r2), "=r"(r3) : "r"(addr));
}

#define CPA16(d, s) asm volatile("cp.async.cg.shared.global [%0], [%1], 16;" :: "r"(d), "l"(s))
#define CP_COMMIT() asm volatile("cp.async.commit_group;")
#define CP_WAIT(n)  asm volatile("cp.async.wait_group %0;" :: "n"(n))

// ---------------------------------------------------------------------------
__global__ void conv_x_kernel(const float* __restrict__ x)
{
    int i = blockIdx.x * blockDim.x + threadIdx.x;
    const float4 v = ((const float4*)x)[i];
    ((uint2*)g_xb)[i] = make_uint2(packh(v.x, v.y), packh(v.z, v.w));
}
__global__ void conv_w_kernel(const float* __restrict__ wq,
                              const float* __restrict__ wk,
                              const float* __restrict__ wv)
{
    int i = blockIdx.x * blockDim.x + threadIdx.x;
    g_wb[i]          = __float2half(wq[i]);
    g_wb[i + 65536]  = __float2half(wk[i]);
    g_wb[i + 131072] = __float2half(wv[i]);
}
__global__ void conv_m_kernel(const unsigned char* __restrict__ xmask)
{
    int i = blockIdx.x * blockDim.x + threadIdx.x;
    int h = i >> 10, t = i & 1023;
    int b = h >> 4,  c = h & 15;
    g_mt[i] = xmask[(size_t)((b << 10) + t) * Cq + c];
}

// ---------------------------------------------------------------------------
// QKV projection, mma.sync f16 with f16 accumulators.
// CTA = 128 M x 256 N (one full matrix), K=256 in 2 phases of 128.
// 8 warps as 2(M) x 4(N): warp tile 64M x 64N.
// smem: X 128x264 halfs @0 (67584B); W0 256x136 @67584; W1 @137216.
// ---------------------------------------------------------------------------
#define QX_OFF 0u
#define QW0_OFF 67584u
#define QW1_OFF 137216u
#define QK_SMEM (137216 + 69632)

__global__ __launch_bounds__(256, 1) void qkv_mma_kernel(
    const int*   __restrict__ pos,
    const float* __restrict__ pe,
    const float* __restrict__ bq,
    const float* __restrict__ bk,
    const float* __restrict__ bv)
{
    extern __shared__ char sm[];
    const unsigned su = (unsigned)__cvta_generic_to_shared(sm);
    const int tid = threadIdx.x, w = tid >> 5, lane = tid & 31;
    const int q = lane & 3, lr = lane >> 2, g = lane >> 3, r8 = lane & 7;
    const int wm = w >> 2, wn = w & 3;
    const int mat = blockIdx.x;
    const int m0  = blockIdx.y * 128;

    // issue X (128x256 halfs) + W half 0, then W half 1
    const __half* xb = g_xb + (size_t)m0 * Dq;
#pragma unroll
    for (int it = 0; it < 16; ++it) {
        int idx = it * 256 + tid;
        int row = idx >> 5, ch = idx & 31;
        CPA16(su + QX_OFF + (unsigned)(row * 528 + ch * 16), xb + row * Dq + ch * 8);
    }
    const __half* wb = g_wb + mat * 65536;
#pragma unroll
    for (int it = 0; it < 16; ++it) {
        int idx = it * 256 + tid;
        int row = idx >> 4, ch = idx & 15;
        CPA16(su + QW0_OFF + (unsigned)(row * 272 + ch * 16), wb + row * Dq + ch * 8);
    }
    CP_COMMIT();
#pragma unroll
    for (int it = 0; it < 16; ++it) {
        int idx = it * 256 + tid;
        int row = idx >> 4, ch = idx & 15;
        CPA16(su + QW1_OFF + (unsigned)(row * 272 + ch * 16), wb + row * Dq + 128 + ch * 8);
    }
    CP_COMMIT();

    unsigned acc[4][8][2];
#pragma unroll
    for (int mt = 0; mt < 4; ++mt)
#pragma unroll
        for (int nt = 0; nt < 8; ++nt) { acc[mt][nt][0] = 0u; acc[mt][nt][1] = 0u; }

    // lane base addresses (validated fragment patterns)
    const unsigned a_base = su + QX_OFF +
        (unsigned)((wm * 64 + (g & 1) * 8 + r8) * 528 + ((g >> 1) * 8) * 2);
    const unsigned b_base = su + QW0_OFF +
        (unsigned)((wn * 64 + (g >> 1) * 8 + r8) * 272 + ((g & 1) * 8) * 2);

#pragma unroll
    for (int ph = 0; ph < 2; ++ph) {
        if (ph == 0) { CP_WAIT(1); } else { CP_WAIT(0); }
        __syncthreads();
        const unsigned ab = a_base + (unsigned)ph * 256u;               // +128 halfs
        const unsigned bb = b_base + (unsigned)ph * (QW1_OFF - QW0_OFF);
#pragma unroll
        for (int kk = 0; kk < 8; ++kk) {
            unsigned af[4][4];
#pragma unroll
            for (int mt = 0; mt < 4; ++mt)
                ldsm_x4(af[mt][0], af[mt][1], af[mt][2], af[mt][3],
                        ab + (unsigned)(mt * 16 * 528) + kk * 32);
#pragma unroll
            for (int nt = 0; nt < 4; ++nt) {
                unsigned b0, b1, b2, b3;
                ldsm_x4(b0, b1, b2, b3, bb + (unsigned)(nt * 16 * 272) + kk * 32);
#pragma unroll
                for (int mt = 0; mt < 4; ++mt) {
                    mma_f16_f16(acc[mt][2*nt][0],   acc[mt][2*nt][1],
                                af[mt][0], af[mt][1], af[mt][2], af[mt][3], b0, b1);
                    mma_f16_f16(acc[mt][2*nt+1][0], acc[mt][2*nt+1][1],
                                af[mt][0], af[mt][1], af[mt][2], af[mt][3], b2, b3);
                }
            }
        }
    }

    // epilogue: bias + RoPE + store
    const float* bias = (mat == 0) ? bq : (mat == 1) ? bk : bv;
    __half* outp = (mat == 0) ? g_q : (mat == 1) ? g_k : g_v;

#pragma unroll
    for (int mt = 0; mt < 4; ++mt) {
        const int tokA = m0 + wm * 64 + mt * 16 + lr;
        const int tokB = tokA + 8;
        const int bA = tokA >> 14, tA = (tokA >> 4) & (Tq-1), cA = tokA & (Cq-1);
        const int bB = tokB >> 14, tB = (tokB >> 4) & (Tq-1), cB = tokB & (Cq-1);
        __half* rowA = outp + ((size_t)(bA * Cq + cA) * Tq + tA) * Dq;
        __half* rowB = outp + ((size_t)(bB * Cq + cB) * Tq + tB) * Dq;
        int pA = 0, pB = 0;
        if (mat < 2) { pA = pos[tokA]; pB = pos[tokB]; }
#pragma unroll
        for (int nt = 0; nt < 8; ++nt) {
            const int col = wn * 64 + nt * 8 + 2 * q;   // even
            const float2 b2 = *(const float2*)(bias + col);
            float2 va = unph(acc[mt][nt][0]);
            float2 vb = unph(acc[mt][nt][1]);
            float v0 = va.x + b2.x, v1 = va.y + b2.y;
            float v2 = vb.x + b2.x, v3 = vb.y + b2.y;
            if (mat < 2) {
                const float2 csA = *(const float2*)(pe + (size_t)pA * Dq + col);
                const float2 csB = *(const float2*)(pe + (size_t)pB * Dq + col);
                float r0 = v0 * csA.x - v1 * csA.y;
                v1 = v0 * csA.y + v1 * csA.x; v0 = r0;
                float r2 = v2 * csB.x - v3 * csB.y;
                v3 = v2 * csB.y + v3 * csB.x; v2 = r2;
            }
            *(unsigned*)&rowA[col] = packh(v0, v1);
            *(unsigned*)&rowB[col] = packh(v2, v3);
        }
    }
}

// ---------------------------------------------------------------------------
// Flash attention (R3, known-good): f16 HMMA f16-acc, Q frags in regs,
// 2-stage cp.async, fused residual + LayerScale + LayerNorm.
// ---------------------------------------------------------------------------
#define STR 264
#define KBYTES (64 * STR * 2)
#define STAGEB (2 * KBYTES)

__global__ __launch_bounds__(256, 1) void attn_tc_kernel(
    const float* __restrict__ x,
    const float* __restrict__ lng,
    const float* __restrict__ lnb,
    const float* __restrict__ lsg,
    float* __restrict__ out)
{
    extern __shared__ char smraw[];
    unsigned char* sQm = (unsigned char*)(smraw + 2 * STAGEB);
    unsigned char* sKm = sQm + 128;
    const unsigned smem_u = (unsigned)__cvta_generic_to_shared(smraw);
    const unsigned sqm_u  = smem_u + 2 * STAGEB;
    const unsigned skm_u  = sqm_u + 128;

    const int tid  = threadIdx.x;
    const int w    = tid >> 5;
    const int lane = tid & 31;
    const int q    = lane & 3;
    const int lr   = lane >> 2;
    const int g    = lane >> 3;
    const int r8   = lane & 7;

    const int h  = blockIdx.y;
    const int b  = h >> 4, c = h & 15;
    const int q0 = blockIdx.x * 128;

    const __half* qg = g_q + ((size_t)h * Tq + q0) * Dq;
    const __half* kg = g_k + (size_t)h * Tq * Dq;
    const __half* vg = g_v + (size_t)h * Tq * Dq;
    const unsigned char* mg = g_mt + h * Tq;

    const unsigned qs = smem_u + STAGEB;
#pragma unroll
    for (int it = 0; it < 16; ++it) {
        int idx = it * 256 + tid;
        int row = idx >> 5, cc = idx & 31;
        CPA16(qs + (unsigned)(row * STR * 2 + cc * 16), qg + row * Dq + cc * 8);
    }
    if (tid < 8) CPA16(sqm_u + tid * 16, mg + q0 + tid * 16);
    CP_COMMIT();
    CP_WAIT(0);
    __syncthreads();

    unsigned qf[16][4];
    const unsigned qa_off = qs +
        ((unsigned)(w * 16 + (g & 1) * 8 + r8) * STR + (g >> 1) * 8) * 2;
#pragma unroll
    for (int kk = 0; kk < 16; ++kk)
        ldsm_x4(qf[kk][0], qf[kk][1], qf[kk][2], qf[kk][3], qa_off + kk * 32);
    const int qmA = sQm[w * 16 + lr];
    const int qmB = sQm[w * 16 + lr + 8];
    __syncthreads();

    auto issue = [&](int kt) {
        const int stage = kt & 1;
        const unsigned sb = smem_u + stage * STAGEB;
        const int k0 = kt * 64;
#pragma unroll
        for (int it = 0; it < 8; ++it) {
            int idx = it * 256 + tid;
            int row = idx >> 5, cc = idx & 31;
            CPA16(sb + (unsigned)(row * STR * 2 + cc * 16),
                  kg + (size_t)(k0 + row) * Dq + cc * 8);
            CPA16(sb + KBYTES + (unsigned)(row * STR * 2 + cc * 16),
                  vg + (size_t)(k0 + row) * Dq + cc * 8);
        }
        if (tid < 4) CPA16(skm_u + stage * 64 + tid * 16, mg + k0 + tid * 16);
    };
    issue(0); CP_COMMIT();
    issue(1); CP_COMMIT();

    const unsigned koff = ((unsigned)((g >> 1) * 8 + r8) * STR + (g & 1) * 8) * 2;
    const unsigned voff = ((unsigned)((g & 1) * 8 + r8) * STR + (g >> 1) * 8) * 2;

    unsigned oacc[32][2];
#pragma unroll
    for (int j = 0; j < 32; ++j) { oacc[j][0] = 0u; oacc[j][1] = 0u; }
    float mrunA = -CUDART_INF_F, mrunB = -CUDART_INF_F;
    float lsumA = 0.f, lsumB = 0.f;

    for (int kt = 0; kt < 16; ++kt) {
        CP_WAIT(1);
        __syncthreads();
        const int stage = kt & 1;
        const unsigned kb_s = smem_u + stage * STAGEB;
        const unsigned vb_s = kb_s + KBYTES;
        const unsigned char* km = sKm + stage * 64;

        unsigned sacc[8][2];
#pragma unroll
        for (int nf = 0; nf < 8; ++nf) { sacc[nf][0] = 0u; sacc[nf][1] = 0u; }
#pragma unroll
        for (int kk = 0; kk < 16; ++kk) {
#pragma unroll
            for (int ng = 0; ng < 4; ++ng) {
                unsigned b0, b1, b2, b3;
                ldsm_x4(b0, b1, b2, b3,
                        kb_s + (unsigned)(ng * 16 * STR * 2) + kk * 32 + koff);
                mma_f16_f16(sacc[2*ng][0],   sacc[2*ng][1],
                            qf[kk][0], qf[kk][1], qf[kk][2], qf[kk][3], b0, b1);
                mma_f16_f16(sacc[2*ng+1][0], sacc[2*ng+1][1],
                            qf[kk][0], qf[kk][1], qf[kk][2], qf[kk][3], b2, b3);
            }
        }

        float sv[8][4];
        float tmaxA = -CUDART_INF_F, tmaxB = -CUDART_INF_F;
#pragma unroll
        for (int nf = 0; nf < 8; ++nf) {
            const float2 lo = unph(sacc[nf][0]);
            const float2 hi = unph(sacc[nf][1]);
            const int cc = nf * 8 + 2 * q;
            const int k0m = km[cc], k1m = km[cc + 1];
            sv[nf][0] = (qmA | k0m) ? -CUDART_INF_F : lo.x * 0.0625f;
            sv[nf][1] = (qmA | k1m) ? -CUDART_INF_F : lo.y * 0.0625f;
            sv[nf][2] = (qmB | k0m) ? -CUDART_INF_F : hi.x * 0.0625f;
            sv[nf][3] = (qmB | k1m) ? -CUDART_INF_F : hi.y * 0.0625f;
            tmaxA = fmaxf(tmaxA, fmaxf(sv[nf][0], sv[nf][1]));
            tmaxB = fmaxf(tmaxB, fmaxf(sv[nf][2], sv[nf][3]));
        }
        tmaxA = fmaxf(tmaxA, __shfl_xor_sync(0xffffffffu, tmaxA, 1));
        tmaxA = fmaxf(tmaxA, __shfl_xor_sync(0xffffffffu, tmaxA, 2));
        tmaxB = fmaxf(tmaxB, __shfl_xor_sync(0xffffffffu, tmaxB, 1));
        tmaxB = fmaxf(tmaxB, __shfl_xor_sync(0xffffffffu, tmaxB, 2));

        const float mnA = fmaxf(mrunA, tmaxA);
        const float mnB = fmaxf(mrunB, tmaxB);
        const float corrA = (mnA == -CUDART_INF_F) ? 1.f : __expf(mrunA - mnA);
        const float corrB = (mnB == -CUDART_INF_F) ? 1.f : __expf(mrunB - mnB);
        const float mUA = (mnA == -CUDART_INF_F) ? 0.f : mnA;
        const float mUB = (mnB == -CUDART_INF_F) ? 0.f : mnB;
        lsumA *= corrA; lsumB *= corrB;
        mrunA = mnA; mrunB = mnB;

        unsigned pa[4][4];
#pragma unroll
        for (int kk = 0; kk < 4; ++kk) {
            float p00 = __expf(sv[2*kk][0]   - mUA);
            float p01 = __expf(sv[2*kk][1]   - mUA);
            float p02 = __expf(sv[2*kk][2]   - mUB);
            float p03 = __expf(sv[2*kk][3]   - mUB);
            float p10 = __expf(sv[2*kk+1][0] - mUA);
            float p11 = __expf(sv[2*kk+1][1] - mUA);
            float p12 = __expf(sv[2*kk+1][2] - mUB);
            float p13 = __expf(sv[2*kk+1][3] - mUB);
            lsumA += p00 + p01 + p10 + p11;
            lsumB += p02 + p03 + p12 + p13;
            pa[kk][0] = packh(p00, p01);
            pa[kk][1] = packh(p02, p03);
            pa[kk][2] = packh(p10, p11);
            pa[kk][3] = packh(p12, p13);
        }

        const unsigned cA2 = packh(corrA, corrA);
        const unsigned cB2 = packh(corrB, corrB);
#pragma unroll
        for (int j = 0; j < 32; ++j) {
            oacc[j][0] = hmul2u(oacc[j][0], cA2);
            oacc[j][1] = hmul2u(oacc[j][1], cB2);
        }

#pragma unroll
        for (int kk = 0; kk < 4; ++kk) {
#pragma unroll
            for (int dg = 0; dg < 16; ++dg) {
                unsigned v0, v1, v2, v3;
                ldsm_x4_t(v0, v1, v2, v3,
                          vb_s + (unsigned)(kk * 16 * STR * 2) + dg * 32 + voff);
                mma_f16_f16(oacc[2*dg][0],   oacc[2*dg][1],
                            pa[kk][0], pa[kk][1], pa[kk][2], pa[kk][3], v0, v1);
                mma_f16_f16(oacc[2*dg+1][0], oacc[2*dg+1][1],
                            pa[kk][0], pa[kk][1], pa[kk][2], pa[kk][3], v2, v3);
            }
        }
        __syncthreads();
        if (kt + 2 < 16) issue(kt + 2);
        CP_COMMIT();
    }

    lsumA += __shfl_xor_sync(0xffffffffu, lsumA, 1);
    lsumA += __shfl_xor_sync(0xffffffffu, lsumA, 2);
    lsumB += __shfl_xor_sync(0xffffffffu, lsumB, 1);
    lsumB += __shfl_xor_sync(0xffffffffu, lsumB, 2);
    const float invA = (lsumA > 0.f) ? (1.f / lsumA) : 0.f;
    const float invB = (lsumB > 0.f) ? (1.f / lsumB) : 0.f;

    const int gtA = q0 + w * 16 + lr;
    const int gtB = gtA + 8;
    const size_t miA = (size_t)(b * Tq + gtA) * Cq + c;
    const size_t miB = (size_t)(b * Tq + gtB) * Cq + c;
    const float* xA = x + miA * Dq;
    const float* xB = x + miB * Dq;

    float yv[32][4];
    float sumA = 0.f, ssqA = 0.f, sumB = 0.f, ssqB = 0.f;
#pragma unroll
    for (int j = 0; j < 32; ++j) {
        const int cc = j * 8 + 2 * q;
        const float2 g2 = *(const float2*)(lsg + cc);
        const float2 xa = *(const float2*)(xA + cc);
        const float2 xb2 = *(const float2*)(xB + cc);
        const float2 oa = unph(oacc[j][0]);
        const float2 ob = unph(oacc[j][1]);
        float y0 = xa.x  + g2.x * (oa.x * invA);
        float y1 = xa.y  + g2.y * (oa.y * invA);
        float y2 = xb2.x + g2.x * (ob.x * invB);
        float y3 = xb2.y + g2.y * (ob.y * invB);
        yv[j][0] = y0; yv[j][1] = y1; yv[j][2] = y2; yv[j][3] = y3;
        sumA += y0 + y1;  ssqA += y0 * y0 + y1 * y1;
        sumB += y2 + y3;  ssqB += y2 * y2 + y3 * y3;
    }
    sumA += __shfl_xor_sync(0xffffffffu, sumA, 1);
    sumA += __shfl_xor_sync(0xffffffffu, sumA, 2);
    ssqA += __shfl_xor_sync(0xffffffffu, ssqA, 1);
    ssqA += __shfl_xor_sync(0xffffffffu, ssqA, 2);
    sumB += __shfl_xor_sync(0xffffffffu, sumB, 1);
    sumB += __shfl_xor_sync(0xffffffffu, sumB, 2);
    ssqB += __shfl_xor_sync(0xffffffffu, ssqB, 1);
    ssqB += __shfl_xor_sync(0xffffffffu, ssqB, 2);

    const float muA = sumA * (1.f / 256.f);
    const float muB = sumB * (1.f / 256.f);
    const float rsA = rsqrtf(ssqA * (1.f / 256.f) - muA * muA + 1e-5f);
    const float rsB = rsqrtf(ssqB * (1.f / 256.f) - muB * muB + 1e-5f);

    float* oA = out + miA * Dq;
    float* oB = out + miB * Dq;
#pragma unroll
    for (int j = 0; j < 32; ++j) {
        const int cc = j * 8 + 2 * q;
        const float2 gg = *(const float2*)(lng + cc);
        const float2 bb = *(const float2*)(lnb + cc);
        float2 r0, r1;
        r0.x = (yv[j][0] - muA) * rsA * gg.x + bb.x;
        r0.y = (yv[j][1] - muA) * rsA * gg.y + bb.y;
        r1.x = (yv[j][2] - muB) * rsB * gg.x + bb.x;
        r1.y = (yv[j][3] - muB) * rsB * gg.y + bb.y;
        *(float2*)(oA + cc) = r0;
        *(float2*)(oB + cc) = r1;
    }
}

// ---------------------------------------------------------------------------
extern "C" void kernel_launch(void* const* d_in, const int* in_sizes, int n_in,
                              void* d_out, int out_size)
{
    const float* x   = (const float*)d_in[0];
    const unsigned char* xmask = (const unsigned char*)d_in[1];
    const int*   pos = (const int*)d_in[2];
    const float* pe  = (const float*)d_in[3];
    const float* wq  = (const float*)d_in[4];
    const float* bq  = (const float*)d_in[5];
    const float* wk  = (const float*)d_in[6];
    const float* bk  = (const float*)d_in[7];
    const float* wv  = (const float*)d_in[8];
    const float* bv  = (const float*)d_in[9];
    const float* lng = (const float*)d_in[10];
    const float* lnb = (const float*)d_in[11];
    const float* lsg = (const float*)d_in[12];
    float* out = (float*)d_out;

    conv_x_kernel<<<(MTOT * Dq / 4) / 256, 256>>>(x);
    conv_w_kernel<<<(Dq * Dq) / 256, 256>>>(wq, wk, wv);
    conv_m_kernel<<<(NHEADS * Tq) / 256, 256>>>(xmask);

    cudaFuncSetAttribute(qkv_mma_kernel,
                         cudaFuncAttributeMaxDynamicSharedMemorySize, QK_SMEM);
    qkv_mma_kernel<<<dim3(3, MTOT / 128), 256, QK_SMEM>>>(pos, pe, bq, bk, bv);

    const int smem2 = 2 * STAGEB + 256;
    cudaFuncSetAttribute(attn_tc_kernel,
                         cudaFuncAttributeMaxDynamicSharedMemorySize, smem2);
    attn_tc_kernel<<<dim3(Tq / 128, NHEADS), 256, smem2>>>(
        x, lng, lnb, lsg, out);
}